// round 4
// baseline (speedup 1.0000x reference)
#include <cuda_runtime.h>
#include <cuda_bf16.h>
#include <cstdint>

#define DT_STEP 0.01f
#define GRID_SMS 152
#define NUM_SLICES 8192                 // 131072 rows / 16
#define WARPS_TOT (GRID_SMS * 16)
#define ROW_B 272                       // 128 bf16 (256B) + 16B pad
#define S_W1  0
#define S_W2  (S_W1 + 128 * ROW_B)
#define S_B1  (S_W2 + 128 * ROW_B)
#define S_B2  (S_B1 + 512)
#define S_TOT (S_B2 + 512)              // 70656 B

// ---------------- helpers ----------------
static __device__ __forceinline__ uint32_t smem_u32(const void* p) {
    uint32_t a;
    asm("{ .reg .u64 t; cvta.to.shared.u64 t, %1; cvt.u32.u64 %0, t; }" : "=r"(a) : "l"(p));
    return a;
}

static __device__ __forceinline__ uint32_t packbf(float a, float b) {
    __nv_bfloat162 t = __floats2bfloat162_rn(a, b);   // .x in low 16 bits
    return *reinterpret_cast<uint32_t*>(&t);
}

static __device__ __forceinline__ float tanh_fast(float v) {
    float r;
    asm("tanh.approx.f32 %0, %1;" : "=f"(r) : "f"(v));
    return r;
}

static __device__ __forceinline__ void ldsm_x4_t(uint32_t* r, uint32_t addr) {
    asm volatile("ldmatrix.sync.aligned.m8n8.x4.trans.shared.b16 {%0,%1,%2,%3}, [%4];"
                 : "=r"(r[0]), "=r"(r[1]), "=r"(r[2]), "=r"(r[3]) : "r"(addr));
}

static __device__ __forceinline__ void mma16816(float* d, const uint32_t* a, const uint32_t* b) {
    asm volatile("mma.sync.aligned.m16n8k16.row.col.f32.bf16.bf16.f32 "
                 "{%0,%1,%2,%3}, {%4,%5,%6,%7}, {%8,%9}, {%0,%1,%2,%3};"
                 : "+f"(d[0]), "+f"(d[1]), "+f"(d[2]), "+f"(d[3])
                 : "r"(a[0]), "r"(a[1]), "r"(a[2]), "r"(a[3]), "r"(b[0]), "r"(b[1]));
}

// ---------------- kernel ----------------
__global__ void __launch_bounds__(512, 1)
koopman_warp(const float* __restrict__ x, const float* __restrict__ W1,
             const float* __restrict__ b1, const float* __restrict__ W2,
             const float* __restrict__ b2, float* __restrict__ out)
{
    extern __shared__ char smem[];
    const uint32_t sb = smem_u32(smem);
    const int tid  = threadIdx.x;
    const int lane = tid & 31;
    const int w    = tid >> 5;          // 0..15
    const int g    = lane >> 2;         // row-in-8
    const int t2   = (lane & 3) * 2;    // col pair

    // ---- one-time: stage W1, W2 (bf16, 16B-padded rows) + biases ----
    #pragma unroll
    for (int j = 0; j < 8; j++) {
        int idx = j * 512 + tid;        // 4096 float4 chunks per matrix
        int r = idx >> 5, c4 = idx & 31;
        float4 wv = *(const float4*)(W1 + (size_t)r * 128 + c4 * 4);
        *(uint2*)(smem + S_W1 + r * ROW_B + c4 * 8) =
            make_uint2(packbf(wv.x, wv.y), packbf(wv.z, wv.w));
        float4 wv2 = *(const float4*)(W2 + (size_t)r * 128 + c4 * 4);
        *(uint2*)(smem + S_W2 + r * ROW_B + c4 * 8) =
            make_uint2(packbf(wv2.x, wv2.y), packbf(wv2.z, wv2.w));
    }
    if (tid < 128) {
        ((float*)(smem + S_B1))[tid] = b1[tid];
        ((float*)(smem + S_B2))[tid] = b2[tid];
    }
    __syncthreads();                    // only CTA-wide sync in the kernel

    const uint32_t wl1 = sb + S_W1 + (uint32_t)lane * ROW_B;
    const uint32_t wl2 = sb + S_W2 + (uint32_t)lane * ROW_B;
    const float* fb1 = (const float*)(smem + S_B1) + t2;
    const float* fb2 = (const float*)(smem + S_B2) + t2;

    // warp-interleaved slice ids: extras spread evenly across SMs
    const int gw = w * GRID_SMS + blockIdx.x;

    for (int s = gw; s < NUM_SLICES; s += WARPS_TOT) {
        const size_t rbase = (size_t)s * 16;
        const float* xg  = x + (rbase + (size_t)g) * 128;
        const float* xg8 = xg + 8 * 128;

        float acc[16][4];
        #pragma unroll
        for (int i = 0; i < 16; i++)
            { acc[i][0] = 0.f; acc[i][1] = 0.f; acc[i][2] = 0.f; acc[i][3] = 0.f; }

        // ---- GEMM1: pre = bf16(x slice) @ W1, A-frags straight from gmem ----
        #pragma unroll
        for (int kh = 0; kh < 2; kh++) {
            uint32_t afr[4][4];
            #pragma unroll
            for (int j = 0; j < 4; j++) {
                int c0 = kh * 64 + j * 16 + t2;
                float2 a0 = *(const float2*)(xg  + c0);
                float2 a1 = *(const float2*)(xg8 + c0);
                float2 a2 = *(const float2*)(xg  + c0 + 8);
                float2 a3 = *(const float2*)(xg8 + c0 + 8);
                afr[j][0] = packbf(a0.x, a0.y);
                afr[j][1] = packbf(a1.x, a1.y);
                afr[j][2] = packbf(a2.x, a2.y);
                afr[j][3] = packbf(a3.x, a3.y);
            }
            #pragma unroll
            for (int nt = 0; nt < 16; nt++) {
                uint32_t b[2][4];
                ldsm_x4_t(b[0], wl1 + (uint32_t)(kh * 2 + 0) * (32 * ROW_B) + nt * 16);
                ldsm_x4_t(b[1], wl1 + (uint32_t)(kh * 2 + 1) * (32 * ROW_B) + nt * 16);
                #pragma unroll
                for (int j = 0; j < 4; j++)
                    mma16816(acc[nt], afr[j], &b[j >> 1][(j & 1) * 2]);
            }
        }

        // ---- epilogue 1 in registers: H-frags = tanh(pre + b1) (A-frag layout!) ----
        uint32_t hfr[16][2];
        #pragma unroll
        for (int nt = 0; nt < 16; nt++) {
            float2 bb = *(const float2*)(fb1 + nt * 8);
            hfr[nt][0] = packbf(tanh_fast(acc[nt][0] + bb.x), tanh_fast(acc[nt][1] + bb.y));
            hfr[nt][1] = packbf(tanh_fast(acc[nt][2] + bb.x), tanh_fast(acc[nt][3] + bb.y));
        }

        #pragma unroll
        for (int i = 0; i < 16; i++)
            { acc[i][0] = 0.f; acc[i][1] = 0.f; acc[i][2] = 0.f; acc[i][3] = 0.f; }

        // ---- GEMM2: pre2 = H @ W2, A-frags from hfr registers (no smem) ----
        #pragma unroll
        for (int kh = 0; kh < 2; kh++) {
            #pragma unroll
            for (int nt = 0; nt < 16; nt++) {
                uint32_t b[2][4];
                ldsm_x4_t(b[0], wl2 + (uint32_t)(kh * 2 + 0) * (32 * ROW_B) + nt * 16);
                ldsm_x4_t(b[1], wl2 + (uint32_t)(kh * 2 + 1) * (32 * ROW_B) + nt * 16);
                #pragma unroll
                for (int j = 0; j < 4; j++) {
                    int kt = kh * 4 + j;
                    uint32_t af[4] = { hfr[2 * kt][0], hfr[2 * kt][1],
                                       hfr[2 * kt + 1][0], hfr[2 * kt + 1][1] };
                    mma16816(acc[nt], af, &b[j >> 1][(j & 1) * 2]);
                }
            }
        }

        // ---- epilogue 2: rotation-scaling on exact fp32 x (re-read from gmem) ----
        #pragma unroll
        for (int nt = 0; nt < 16; nt++) {
            int c = nt * 8 + t2;
            float2 bb = *(const float2*)(fb2 + nt * 8);
            #pragma unroll
            for (int half = 0; half < 2; half++) {
                float mu = acc[nt][half * 2 + 0] + bb.x;
                float om = acc[nt][half * 2 + 1] + bb.y;
                const float* xr = half ? xg8 : xg;
                float2 xv = *(const float2*)(xr + c);
                float z  = DT_STEP * mu;
                float e  = fmaf(z, fmaf(z, fmaf(z, 1.f / 6.f, 0.5f), 1.f), 1.f);
                float wv = DT_STEP * om;
                float w2 = wv * wv;
                float sn = wv * fmaf(w2, -1.f / 6.f, 1.f);
                float cs = fmaf(w2, fmaf(w2, 1.f / 24.f, -0.5f), 1.f);
                float2 o;
                o.x = e * (cs * xv.x - sn * xv.y);
                o.y = e * (sn * xv.x + cs * xv.y);
                size_t r = rbase + (size_t)g + (size_t)half * 8;
                *(float2*)(out + r * 128 + c) = o;
            }
        }
    }
}

// ---------------- launch ----------------
extern "C" void kernel_launch(void* const* d_in, const int* in_sizes, int n_in,
                              void* d_out, int out_size) {
    const float* x  = (const float*)d_in[0];
    const float* W1 = (const float*)d_in[1];
    const float* b1 = (const float*)d_in[2];
    const float* W2 = (const float*)d_in[3];
    const float* b2 = (const float*)d_in[4];
    float* out = (float*)d_out;

    cudaFuncSetAttribute(koopman_warp,
                         cudaFuncAttributeMaxDynamicSharedMemorySize, S_TOT);
    koopman_warp<<<GRID_SMS, 512, S_TOT>>>(x, W1, b1, W2, b2, out);
}

// round 5
// speedup vs baseline: 1.0749x; 1.0749x over previous
#include <cuda_runtime.h>
#include <cuda_bf16.h>
#include <cstdint>

#define DT_STEP 0.01f
#define GRID_SMS 152
#define NUM_SLICES 8192                 // 131072 rows / 16
#define NUM_QUADS (GRID_SMS * 2)        // 304
#define ROW_B 272                       // 128 bf16 (256B) + 16B pad
#define T16 (16 * ROW_B)                // one 16-row tile = 4352 B

#define S_W1  0
#define S_W2  (S_W1 + 128 * ROW_B)
#define S_B1  (S_W2 + 128 * ROW_B)
#define S_B2  (S_B1 + 512)
#define S_T   (S_B2 + 512)              // per-quad tiles start here
#define PER_Q (5 * T16)                 // hi0, hi1, lo0, lo1, H
#define S_TOT (S_T + 2 * PER_Q)         // 70656 + 43520 = 114176 B

// ---------------- helpers ----------------
static __device__ __forceinline__ uint32_t smem_u32(const void* p) {
    uint32_t a;
    asm("{ .reg .u64 t; cvta.to.shared.u64 t, %1; cvt.u32.u64 %0, t; }" : "=r"(a) : "l"(p));
    return a;
}

static __device__ __forceinline__ uint32_t packbf(float a, float b) {
    __nv_bfloat162 t = __floats2bfloat162_rn(a, b);   // .x in low 16 bits
    return *reinterpret_cast<uint32_t*>(&t);
}

static __device__ __forceinline__ void split2(float a, float b, uint32_t& hi, uint32_t& lo) {
    float ah = __bfloat162float(__float2bfloat16_rn(a));
    float bh = __bfloat162float(__float2bfloat16_rn(b));
    hi = packbf(a, b);
    lo = packbf(a - ah, b - bh);
}

static __device__ __forceinline__ __nv_bfloat162 u2bf(uint32_t v) {
    return *reinterpret_cast<__nv_bfloat162*>(&v);
}

static __device__ __forceinline__ float tanh_fast(float v) {
    float r;
    asm("tanh.approx.f32 %0, %1;" : "=f"(r) : "f"(v));
    return r;
}

static __device__ __forceinline__ void ldsm_x4(uint32_t* r, uint32_t addr) {
    asm volatile("ldmatrix.sync.aligned.m8n8.x4.shared.b16 {%0,%1,%2,%3}, [%4];"
                 : "=r"(r[0]), "=r"(r[1]), "=r"(r[2]), "=r"(r[3]) : "r"(addr));
}

static __device__ __forceinline__ void ldsm_x4_t(uint32_t* r, uint32_t addr) {
    asm volatile("ldmatrix.sync.aligned.m8n8.x4.trans.shared.b16 {%0,%1,%2,%3}, [%4];"
                 : "=r"(r[0]), "=r"(r[1]), "=r"(r[2]), "=r"(r[3]) : "r"(addr));
}

static __device__ __forceinline__ void mma16816(float* d, const uint32_t* a, const uint32_t* b) {
    asm volatile("mma.sync.aligned.m16n8k16.row.col.f32.bf16.bf16.f32 "
                 "{%0,%1,%2,%3}, {%4,%5,%6,%7}, {%8,%9}, {%0,%1,%2,%3};"
                 : "+f"(d[0]), "+f"(d[1]), "+f"(d[2]), "+f"(d[3])
                 : "r"(a[0]), "r"(a[1]), "r"(a[2]), "r"(a[3]), "r"(b[0]), "r"(b[1]));
}

// ---------------- kernel ----------------
__global__ void __launch_bounds__(256, 1)
koopman_bstat(const float* __restrict__ x, const float* __restrict__ W1,
              const float* __restrict__ b1, const float* __restrict__ W2,
              const float* __restrict__ b2, float* __restrict__ out)
{
    extern __shared__ char smem[];
    const uint32_t sb = smem_u32(smem);
    const int tid  = threadIdx.x;
    const int lane = tid & 31;
    const int w    = tid >> 5;          // 0..7
    const int quad = w >> 2;            // 0..1
    const int qw   = w & 3;             // N-quarter owner
    const int g    = lane >> 2;
    const int t2   = (lane & 3) * 2;
    const int barid = quad + 1;

    // ---- one-time: stage W1, W2 (bf16) + biases ----
    #pragma unroll
    for (int j = 0; j < 16; j++) {
        int idx = j * 256 + tid;        // 4096 float4 chunks per matrix
        int r = idx >> 5, c4 = idx & 31;
        float4 wv = *(const float4*)(W1 + (size_t)r * 128 + c4 * 4);
        *(uint2*)(smem + S_W1 + r * ROW_B + c4 * 8) =
            make_uint2(packbf(wv.x, wv.y), packbf(wv.z, wv.w));
        float4 wv2 = *(const float4*)(W2 + (size_t)r * 128 + c4 * 4);
        *(uint2*)(smem + S_W2 + r * ROW_B + c4 * 8) =
            make_uint2(packbf(wv2.x, wv2.y), packbf(wv2.z, wv2.w));
    }
    if (tid < 128) {
        ((float*)(smem + S_B1))[tid] = b1[tid];
        ((float*)(smem + S_B2))[tid] = b2[tid];
    }
    __syncthreads();

    // ---- load this warp's stationary B-fragments (N-quarter of W1 and W2) ----
    uint32_t B1f[4][4][4], B2f[4][4][4];     // [ntl][q(k32 group)][4 regs]
    {
        uint32_t wl1 = sb + S_W1 + (uint32_t)lane * ROW_B + (uint32_t)qw * 64;
        uint32_t wl2 = sb + S_W2 + (uint32_t)lane * ROW_B + (uint32_t)qw * 64;
        #pragma unroll
        for (int ntl = 0; ntl < 4; ntl++)
            #pragma unroll
            for (int q = 0; q < 4; q++) {
                ldsm_x4_t(B1f[ntl][q], wl1 + (uint32_t)q * (32 * ROW_B) + ntl * 16);
                ldsm_x4_t(B2f[ntl][q], wl2 + (uint32_t)q * (32 * ROW_B) + ntl * 16);
            }
    }

    const uint32_t tb   = sb + S_T + (uint32_t)quad * PER_Q;
    const uint32_t hiB  = tb;                 // hi0, hi1
    const uint32_t loB  = tb + 2 * T16;       // lo0, lo1
    const uint32_t hB   = tb + 4 * T16;       // H tile
    const int cq = qw * 32;                   // this warp's column base
    const float* fb1 = (const float*)(smem + S_B1) + cq + t2;
    const float* fb2 = (const float*)(smem + S_B2) + cq + t2;

    const int qid = blockIdx.x * 2 + quad;

    // ---- stage first slice's x into buffer 0 (4 rows per warp) ----
    {
        const float* xr = x + ((size_t)qid * 16 + qw * 4) * 128 + lane * 4;
        #pragma unroll
        for (int i = 0; i < 4; i++) {
            float4 v = *(const float4*)(xr + (size_t)i * 128);
            uint32_t h0, l0, h1, l1;
            split2(v.x, v.y, h0, l0);
            split2(v.z, v.w, h1, l1);
            int r = qw * 4 + i;
            *(uint2*)(smem + (hiB - sb) + r * ROW_B + lane * 8) = make_uint2(h0, h1);
            *(uint2*)(smem + (loB - sb) + r * ROW_B + lane * 8) = make_uint2(l0, l1);
        }
    }
    asm volatile("bar.sync %0, 128;" :: "r"(barid) : "memory");

    const uint32_t amRow = (uint32_t)((lane & 7) + ((lane >> 3) & 1) * 8) * ROW_B
                         + (uint32_t)(lane >> 4) * 16;

    int buf = 0;
    for (int s = qid; s < NUM_SLICES; s += NUM_QUADS) {
        const size_t rbase = (size_t)s * 16;
        const uint32_t hi = hiB + (uint32_t)buf * T16;
        const uint32_t lo = loB + (uint32_t)buf * T16;

        // ---- prefetch next slice's x (LDG now, STS later) ----
        const bool has_next = (s + NUM_QUADS < NUM_SLICES);
        float4 v[4];
        if (has_next) {
            const float* xr = x + ((size_t)(s + NUM_QUADS) * 16 + qw * 4) * 128 + lane * 4;
            #pragma unroll
            for (int i = 0; i < 4; i++) v[i] = *(const float4*)(xr + (size_t)i * 128);
        }

        float acc[4][4];
        #pragma unroll
        for (int i = 0; i < 4; i++)
            { acc[i][0] = 0.f; acc[i][1] = 0.f; acc[i][2] = 0.f; acc[i][3] = 0.f; }

        // ---- GEMM1: acc = Xhi(16 rows) @ W1(:, quarter), B in registers ----
        #pragma unroll
        for (int kh = 0; kh < 2; kh++) {
            uint32_t afr[4][4];
            #pragma unroll
            for (int j = 0; j < 4; j++)
                ldsm_x4(afr[j], hi + amRow + (uint32_t)(kh * 4 + j) * 32);
            #pragma unroll
            for (int ntl = 0; ntl < 4; ntl++)
                #pragma unroll
                for (int j = 0; j < 4; j++)
                    mma16816(acc[ntl], afr[j], &B1f[ntl][kh * 2 + (j >> 1)][(j & 1) * 2]);
        }

        // ---- epilogue 1: H quarter = tanh(acc + b1) -> smem ----
        #pragma unroll
        for (int ntl = 0; ntl < 4; ntl++) {
            float2 bb = *(const float2*)(fb1 + ntl * 8);
            int c = cq + ntl * 8 + t2;
            uint32_t p0 = packbf(tanh_fast(acc[ntl][0] + bb.x), tanh_fast(acc[ntl][1] + bb.y));
            uint32_t p1 = packbf(tanh_fast(acc[ntl][2] + bb.x), tanh_fast(acc[ntl][3] + bb.y));
            *(uint32_t*)(smem + (hB - sb) + g * ROW_B + c * 2) = p0;
            *(uint32_t*)(smem + (hB - sb) + (g + 8) * ROW_B + c * 2) = p1;
        }

        // ---- stage next slice's x into the other buffer (LDG latency now hidden) ----
        if (has_next) {
            uint32_t hi2 = (hiB - sb) + (uint32_t)(buf ^ 1) * T16;
            uint32_t lo2 = (loB - sb) + (uint32_t)(buf ^ 1) * T16;
            #pragma unroll
            for (int i = 0; i < 4; i++) {
                uint32_t h0, l0, h1, l1;
                split2(v[i].x, v[i].y, h0, l0);
                split2(v[i].z, v[i].w, h1, l1);
                int r = qw * 4 + i;
                *(uint2*)(smem + hi2 + r * ROW_B + lane * 8) = make_uint2(h0, h1);
                *(uint2*)(smem + lo2 + r * ROW_B + lane * 8) = make_uint2(l0, l1);
            }
        }
        asm volatile("bar.sync %0, 128;" :: "r"(barid) : "memory");   // H ready

        // ---- GEMM2: acc = H(16 rows, full K) @ W2(:, quarter) ----
        #pragma unroll
        for (int i = 0; i < 4; i++)
            { acc[i][0] = 0.f; acc[i][1] = 0.f; acc[i][2] = 0.f; acc[i][3] = 0.f; }
        #pragma unroll
        for (int kh = 0; kh < 2; kh++) {
            uint32_t afr[4][4];
            #pragma unroll
            for (int j = 0; j < 4; j++)
                ldsm_x4(afr[j], hB + amRow + (uint32_t)(kh * 4 + j) * 32);
            #pragma unroll
            for (int ntl = 0; ntl < 4; ntl++)
                #pragma unroll
                for (int j = 0; j < 4; j++)
                    mma16816(acc[ntl], afr[j], &B2f[ntl][kh * 2 + (j >> 1)][(j & 1) * 2]);
        }

        // ---- epilogue 2: rotation-scaling on fp32 x (hi+lo from smem) ----
        #pragma unroll
        for (int ntl = 0; ntl < 4; ntl++) {
            int c = cq + ntl * 8 + t2;
            float2 bb = *(const float2*)(fb2 + ntl * 8);
            #pragma unroll
            for (int half = 0; half < 2; half++) {
                float mu = acc[ntl][half * 2 + 0] + bb.x;
                float om = acc[ntl][half * 2 + 1] + bb.y;
                int r = g + half * 8;
                uint32_t xh = *(const uint32_t*)(smem + (hi - sb) + r * ROW_B + c * 2);
                uint32_t xl = *(const uint32_t*)(smem + (lo - sb) + r * ROW_B + c * 2);
                __nv_bfloat162 hh = u2bf(xh), ll = u2bf(xl);
                float xe = __low2float(hh)  + __low2float(ll);
                float xo = __high2float(hh) + __high2float(ll);
                float z  = DT_STEP * mu;
                float e  = fmaf(z, fmaf(z, fmaf(z, 1.f / 6.f, 0.5f), 1.f), 1.f);
                float wv = DT_STEP * om;
                float w2 = wv * wv;
                float sn = wv * fmaf(w2, -1.f / 6.f, 1.f);
                float cs = fmaf(w2, fmaf(w2, 1.f / 24.f, -0.5f), 1.f);
                float2 o;
                o.x = e * (cs * xe - sn * xo);
                o.y = e * (sn * xe + cs * xo);
                *(float2*)(out + (rbase + (size_t)r) * 128 + c) = o;
            }
        }
        asm volatile("bar.sync %0, 128;" :: "r"(barid) : "memory");   // H/x reuse safe
        buf ^= 1;
    }
}

// ---------------- launch ----------------
extern "C" void kernel_launch(void* const* d_in, const int* in_sizes, int n_in,
                              void* d_out, int out_size) {
    const float* x  = (const float*)d_in[0];
    const float* W1 = (const float*)d_in[1];
    const float* b1 = (const float*)d_in[2];
    const float* W2 = (const float*)d_in[3];
    const float* b2 = (const float*)d_in[4];
    float* out = (float*)d_out;

    cudaFuncSetAttribute(koopman_bstat,
                         cudaFuncAttributeMaxDynamicSharedMemorySize, S_TOT);
    koopman_bstat<<<GRID_SMS, 256, S_TOT>>>(x, W1, b1, W2, b2, out);
}

// round 6
// speedup vs baseline: 1.1952x; 1.1119x over previous
#include <cuda_runtime.h>
#include <cuda_bf16.h>
#include <cstdint>

#define DT_STEP 0.01f
#define GRID_SMS 152
#define NUM_SLICES 8192                 // 131072 rows / 16
#define STRIDE (GRID_SMS * 16)          // 2432 warps total
#define ROW_B 272                       // 128 bf16 (256B) + 16B pad
#define T16 (16 * ROW_B)                // 16-row strip = 4352 B

#define S_W1  0
#define S_W2  (S_W1 + 128 * ROW_B)
#define S_B1  (S_W2 + 128 * ROW_B)
#define S_B2  (S_B1 + 512)
#define S_X   (S_B2 + 512)              // 16 warps x (hi strip + lo strip)
#define S_TOT (S_X + 16 * 2 * T16)      // 70656 + 139264 = 209920 B

// ---------------- helpers ----------------
static __device__ __forceinline__ uint32_t smem_u32(const void* p) {
    uint32_t a;
    asm("{ .reg .u64 t; cvta.to.shared.u64 t, %1; cvt.u32.u64 %0, t; }" : "=r"(a) : "l"(p));
    return a;
}

static __device__ __forceinline__ uint32_t packbf(float a, float b) {
    __nv_bfloat162 t = __floats2bfloat162_rn(a, b);   // .x in low 16 bits
    return *reinterpret_cast<uint32_t*>(&t);
}

static __device__ __forceinline__ void split2(float a, float b, uint32_t& hi, uint32_t& lo) {
    float ah = __bfloat162float(__float2bfloat16_rn(a));
    float bh = __bfloat162float(__float2bfloat16_rn(b));
    hi = packbf(a, b);
    lo = packbf(a - ah, b - bh);
}

static __device__ __forceinline__ __nv_bfloat162 u2bf(uint32_t v) {
    return *reinterpret_cast<__nv_bfloat162*>(&v);
}

static __device__ __forceinline__ float tanh_fast(float v) {
    float r;
    asm("tanh.approx.f32 %0, %1;" : "=f"(r) : "f"(v));
    return r;
}

static __device__ __forceinline__ void ldsm_x4(uint32_t* r, uint32_t addr) {
    asm volatile("ldmatrix.sync.aligned.m8n8.x4.shared.b16 {%0,%1,%2,%3}, [%4];"
                 : "=r"(r[0]), "=r"(r[1]), "=r"(r[2]), "=r"(r[3]) : "r"(addr));
}

static __device__ __forceinline__ void ldsm_x4_t(uint32_t* r, uint32_t addr) {
    asm volatile("ldmatrix.sync.aligned.m8n8.x4.trans.shared.b16 {%0,%1,%2,%3}, [%4];"
                 : "=r"(r[0]), "=r"(r[1]), "=r"(r[2]), "=r"(r[3]) : "r"(addr));
}

static __device__ __forceinline__ void mma16816(float* d, const uint32_t* a, const uint32_t* b) {
    asm volatile("mma.sync.aligned.m16n8k16.row.col.f32.bf16.bf16.f32 "
                 "{%0,%1,%2,%3}, {%4,%5,%6,%7}, {%8,%9}, {%0,%1,%2,%3};"
                 : "+f"(d[0]), "+f"(d[1]), "+f"(d[2]), "+f"(d[3])
                 : "r"(a[0]), "r"(a[1]), "r"(a[2]), "r"(a[3]), "r"(b[0]), "r"(b[1]));
}

// ---------------- kernel ----------------
__global__ void __launch_bounds__(512, 1)
koopman_regh(const float* __restrict__ x, const float* __restrict__ W1,
             const float* __restrict__ b1, const float* __restrict__ W2,
             const float* __restrict__ b2, float* __restrict__ out)
{
    extern __shared__ char smem[];
    const uint32_t sb = smem_u32(smem);
    const int tid  = threadIdx.x;
    const int lane = tid & 31;
    const int w    = tid >> 5;          // 0..15
    const int g    = lane >> 2;
    const int t2   = (lane & 3) * 2;

    // ---- one-time: stage W1, W2 (bf16, padded rows) + biases ----
    #pragma unroll
    for (int j = 0; j < 8; j++) {
        int idx = j * 512 + tid;        // 4096 float4 chunks per matrix
        int r = idx >> 5, c4 = idx & 31;
        float4 wv = *(const float4*)(W1 + (size_t)r * 128 + c4 * 4);
        *(uint2*)(smem + S_W1 + r * ROW_B + c4 * 8) =
            make_uint2(packbf(wv.x, wv.y), packbf(wv.z, wv.w));
        float4 wv2 = *(const float4*)(W2 + (size_t)r * 128 + c4 * 4);
        *(uint2*)(smem + S_W2 + r * ROW_B + c4 * 8) =
            make_uint2(packbf(wv2.x, wv2.y), packbf(wv2.z, wv2.w));
    }
    if (tid < 128) {
        ((float*)(smem + S_B1))[tid] = b1[tid];
        ((float*)(smem + S_B2))[tid] = b2[tid];
    }
    __syncthreads();                    // only CTA-wide sync in the kernel

    const uint32_t wl1 = sb + S_W1 + (uint32_t)lane * ROW_B;
    const uint32_t wl2 = sb + S_W2 + (uint32_t)lane * ROW_B;
    const float* fb1 = (const float*)(smem + S_B1) + t2;
    const float* fb2 = (const float*)(smem + S_B2) + t2;

    const uint32_t xhi = (uint32_t)(S_X + w * 2 * T16);   // warp-private strips
    const uint32_t xlo = xhi + T16;
    const uint32_t amRow = (uint32_t)((lane & 7) + ((lane >> 3) & 1) * 8) * ROW_B
                         + (uint32_t)(lane >> 4) * 16;

    // warp-global id: extras spread evenly across SMs (per-SM tail = 0.2%)
    for (int s = w * GRID_SMS + blockIdx.x; s < NUM_SLICES; s += STRIDE) {
        const size_t rbase = (size_t)s * 16;

        // ---- stage this warp's 16 x-rows (coalesced LDG.128 -> hi/lo STS) ----
        {
            const float* xr = x + rbase * 128 + lane * 4;
            #pragma unroll
            for (int i = 0; i < 16; i++) {
                float4 v = *(const float4*)(xr + (size_t)i * 128);
                uint32_t h0, l0, h1, l1;
                split2(v.x, v.y, h0, l0);
                split2(v.z, v.w, h1, l1);
                *(uint2*)(smem + xhi + i * ROW_B + lane * 8) = make_uint2(h0, h1);
                *(uint2*)(smem + xlo + i * ROW_B + lane * 8) = make_uint2(l0, l1);
            }
        }
        __syncwarp();

        // ---- A-frags for GEMM1 from warp-private hi strip ----
        uint32_t afr[8][4];
        #pragma unroll
        for (int kt = 0; kt < 8; kt++)
            ldsm_x4(afr[kt], sb + xhi + amRow + (uint32_t)kt * 32);

        // ---- GEMM1: pre = Xhi(16 rows) @ W1 (full N=128) ----
        float acc[16][4];
        #pragma unroll
        for (int i = 0; i < 16; i++)
            { acc[i][0] = 0.f; acc[i][1] = 0.f; acc[i][2] = 0.f; acc[i][3] = 0.f; }
        #pragma unroll
        for (int nt = 0; nt < 16; nt++) {
            uint32_t b[4][4];
            #pragma unroll
            for (int q = 0; q < 4; q++)
                ldsm_x4_t(b[q], wl1 + (uint32_t)q * (32 * ROW_B) + nt * 16);
            #pragma unroll
            for (int kt = 0; kt < 8; kt++)
                mma16816(acc[nt], afr[kt], &b[kt >> 1][(kt & 1) * 2]);
        }

        // ---- epilogue 1 in registers: H-frags = tanh(pre + b1) (A-frag layout) ----
        uint32_t hfr[16][2];
        #pragma unroll
        for (int nt = 0; nt < 16; nt++) {
            float2 bb = *(const float2*)(fb1 + nt * 8);
            hfr[nt][0] = packbf(tanh_fast(acc[nt][0] + bb.x), tanh_fast(acc[nt][1] + bb.y));
            hfr[nt][1] = packbf(tanh_fast(acc[nt][2] + bb.x), tanh_fast(acc[nt][3] + bb.y));
        }

        // ---- GEMM2: pre2 = H @ W2, A straight from hfr registers ----
        #pragma unroll
        for (int i = 0; i < 16; i++)
            { acc[i][0] = 0.f; acc[i][1] = 0.f; acc[i][2] = 0.f; acc[i][3] = 0.f; }
        #pragma unroll
        for (int nt = 0; nt < 16; nt++) {
            uint32_t b[4][4];
            #pragma unroll
            for (int q = 0; q < 4; q++)
                ldsm_x4_t(b[q], wl2 + (uint32_t)q * (32 * ROW_B) + nt * 16);
            #pragma unroll
            for (int kt = 0; kt < 8; kt++) {
                uint32_t af[4] = { hfr[2 * kt][0], hfr[2 * kt][1],
                                   hfr[2 * kt + 1][0], hfr[2 * kt + 1][1] };
                mma16816(acc[nt], af, &b[kt >> 1][(kt & 1) * 2]);
            }
        }

        // ---- epilogue 2: rotation-scaling on fp32 x (hi+lo from private strip) ----
        #pragma unroll
        for (int nt = 0; nt < 16; nt++) {
            int c = nt * 8 + t2;
            float2 bb = *(const float2*)(fb2 + nt * 8);
            #pragma unroll
            for (int half = 0; half < 2; half++) {
                float mu = acc[nt][half * 2 + 0] + bb.x;
                float om = acc[nt][half * 2 + 1] + bb.y;
                int r = g + half * 8;
                uint32_t xh = *(const uint32_t*)(smem + xhi + r * ROW_B + c * 2);
                uint32_t xl = *(const uint32_t*)(smem + xlo + r * ROW_B + c * 2);
                __nv_bfloat162 hh = u2bf(xh), ll = u2bf(xl);
                float xe = __low2float(hh)  + __low2float(ll);
                float xo = __high2float(hh) + __high2float(ll);
                float z  = DT_STEP * mu;
                float e  = fmaf(z, fmaf(z, fmaf(z, 1.f / 6.f, 0.5f), 1.f), 1.f);
                float wv = DT_STEP * om;
                float w2 = wv * wv;
                float sn = wv * fmaf(w2, -1.f / 6.f, 1.f);
                float cs = fmaf(w2, fmaf(w2, 1.f / 24.f, -0.5f), 1.f);
                float2 o;
                o.x = e * (cs * xe - sn * xo);
                o.y = e * (sn * xe + cs * xo);
                *(float2*)(out + (rbase + (size_t)r) * 128 + c) = o;
            }
        }
        __syncwarp();   // strip reuse safe (warp-local)
    }
}

// ---------------- launch ----------------
extern "C" void kernel_launch(void* const* d_in, const int* in_sizes, int n_in,
                              void* d_out, int out_size) {
    const float* x  = (const float*)d_in[0];
    const float* W1 = (const float*)d_in[1];
    const float* b1 = (const float*)d_in[2];
    const float* W2 = (const float*)d_in[3];
    const float* b2 = (const float*)d_in[4];
    float* out = (float*)d_out;

    cudaFuncSetAttribute(koopman_regh,
                         cudaFuncAttributeMaxDynamicSharedMemorySize, S_TOT);
    koopman_regh<<<GRID_SMS, 512, S_TOT>>>(x, W1, b1, W2, b2, out);
}

// round 8
// speedup vs baseline: 1.2872x; 1.0769x over previous
#include <cuda_runtime.h>
#include <cuda_bf16.h>
#include <cstdint>

#define DT_STEP 0.01f
#define GRID_SMS 152
#define NUM_S32 4096                    // 131072 rows / 32
#define NUM_QUADS (GRID_SMS * 4)        // 608
#define ROW_B 272                       // 128 bf16 (256B) + 16B pad
#define T32 (32 * ROW_B)                // 32-row strip = 8704 B

#define S_W1  0
#define S_W2  (S_W1 + 128 * ROW_B)
#define S_B1  (S_W2 + 128 * ROW_B)
#define S_B2  (S_B1 + 512)
#define S_Q   (S_B2 + 512)              // 4 quads x (xhi0, xhi1, H)
#define S_TOT (S_Q + 4 * 3 * T32)       // 70656 + 104448 = 175104 B

// ---------------- helpers ----------------
static __device__ __forceinline__ uint32_t smem_u32(const void* p) {
    uint32_t a;
    asm("{ .reg .u64 t; cvta.to.shared.u64 t, %1; cvt.u32.u64 %0, t; }" : "=r"(a) : "l"(p));
    return a;
}

static __device__ __forceinline__ uint32_t packbf(float a, float b) {
    __nv_bfloat162 t = __floats2bfloat162_rn(a, b);   // .x in low 16 bits
    return *reinterpret_cast<uint32_t*>(&t);
}

static __device__ __forceinline__ float tanh_fast(float v) {
    float r;
    asm("tanh.approx.f32 %0, %1;" : "=f"(r) : "f"(v));
    return r;
}

static __device__ __forceinline__ void ldsm_x4(uint32_t* r, uint32_t addr) {
    asm volatile("ldmatrix.sync.aligned.m8n8.x4.shared.b16 {%0,%1,%2,%3}, [%4];"
                 : "=r"(r[0]), "=r"(r[1]), "=r"(r[2]), "=r"(r[3]) : "r"(addr));
}

static __device__ __forceinline__ void ldsm_x4_t(uint32_t* r, uint32_t addr) {
    asm volatile("ldmatrix.sync.aligned.m8n8.x4.trans.shared.b16 {%0,%1,%2,%3}, [%4];"
                 : "=r"(r[0]), "=r"(r[1]), "=r"(r[2]), "=r"(r[3]) : "r"(addr));
}

static __device__ __forceinline__ void mma16816(float* d, const uint32_t* a, const uint32_t* b) {
    asm volatile("mma.sync.aligned.m16n8k16.row.col.f32.bf16.bf16.f32 "
                 "{%0,%1,%2,%3}, {%4,%5,%6,%7}, {%8,%9}, {%0,%1,%2,%3};"
                 : "+f"(d[0]), "+f"(d[1]), "+f"(d[2]), "+f"(d[3])
                 : "r"(a[0]), "r"(a[1]), "r"(a[2]), "r"(a[3]), "r"(b[0]), "r"(b[1]));
}

// ---------------- kernel ----------------
__global__ void __launch_bounds__(512, 1)
koopman_quad2(const float* __restrict__ x, const float* __restrict__ W1,
              const float* __restrict__ b1, const float* __restrict__ W2,
              const float* __restrict__ b2, float* __restrict__ out)
{
    extern __shared__ char smem[];
    const uint32_t sb = smem_u32(smem);
    const int tid  = threadIdx.x;
    const int lane = tid & 31;
    const int w    = tid >> 5;          // 0..15
    const int quad = w >> 2;            // 0..3
    const int qw   = w & 3;             // N-quarter owner
    const int g    = lane >> 2;
    const int t2   = (lane & 3) * 2;
    const int barid = quad + 1;

    // ---- one-time: stage W1, W2 (bf16, padded rows) + biases ----
    #pragma unroll
    for (int j = 0; j < 8; j++) {
        int idx = j * 512 + tid;        // 4096 float4 chunks per matrix
        int r = idx >> 5, c4 = idx & 31;
        float4 wv = *(const float4*)(W1 + (size_t)r * 128 + c4 * 4);
        *(uint2*)(smem + S_W1 + r * ROW_B + c4 * 8) =
            make_uint2(packbf(wv.x, wv.y), packbf(wv.z, wv.w));
        float4 wv2 = *(const float4*)(W2 + (size_t)r * 128 + c4 * 4);
        *(uint2*)(smem + S_W2 + r * ROW_B + c4 * 8) =
            make_uint2(packbf(wv2.x, wv2.y), packbf(wv2.z, wv2.w));
    }
    if (tid < 128) {
        ((float*)(smem + S_B1))[tid] = b1[tid];
        ((float*)(smem + S_B2))[tid] = b2[tid];
    }
    __syncthreads();                    // only CTA-wide sync

    // offsets are PURE offsets; C-pointer access = smem + off, ldsm = sb + off
    const uint32_t qoff = (uint32_t)(S_Q + quad * 3 * T32);
    const uint32_t hoff = qoff + 2 * T32;                 // H strip (32 x 128)
    const uint32_t wl1 = sb + S_W1 + (uint32_t)lane * ROW_B + (uint32_t)qw * 64;
    const uint32_t wl2 = sb + S_W2 + (uint32_t)lane * ROW_B + (uint32_t)qw * 64;
    const float* fb1 = (const float*)(smem + S_B1) + qw * 32 + t2;
    const float* fb2 = (const float*)(smem + S_B2) + qw * 32 + t2;

    const uint32_t amBase = (uint32_t)((lane & 7) + ((lane >> 3) & 1) * 8) * ROW_B
                          + (uint32_t)(lane >> 4) * 16;
    const int srow = qw * 8;                              // this warp's staging rows

    const int qid = blockIdx.x * 4 + quad;

    // ---- stage first slice's x (hi bf16) into buffer 0 ----
    {
        const float* xr = x + ((size_t)qid * 32 + srow) * 128 + lane * 4;
        #pragma unroll
        for (int i = 0; i < 8; i++) {
            float4 v = *(const float4*)(xr + (size_t)i * 128);
            *(uint2*)(smem + qoff + (srow + i) * ROW_B + lane * 8) =
                make_uint2(packbf(v.x, v.y), packbf(v.z, v.w));
        }
    }
    asm volatile("bar.sync %0, 128;" :: "r"(barid) : "memory");

    int buf = 0;
    for (int s = qid; s < NUM_S32; s += NUM_QUADS) {
        const size_t rbase = (size_t)s * 32;
        const uint32_t xcur = qoff + (uint32_t)buf * T32;
        const uint32_t xnxt = qoff + (uint32_t)(buf ^ 1) * T32;
        const bool hn = (s + NUM_QUADS < NUM_S32);
        const float* xnp = x + ((size_t)(s + NUM_QUADS) * 32 + srow) * 128 + lane * 4;

        // prefetch first 4 rows of next slice (hide LDG under GEMM1)
        float4 v0[4];
        if (hn) {
            #pragma unroll
            for (int i = 0; i < 4; i++) v0[i] = *(const float4*)(xnp + (size_t)i * 128);
        }

        // ---- GEMM1: acc = Xhi(32 rows) @ W1(:, quarter) ----
        float acc[4][2][4];
        #pragma unroll
        for (int nt = 0; nt < 4; nt++)
            #pragma unroll
            for (int mt = 0; mt < 2; mt++)
                { acc[nt][mt][0]=0.f; acc[nt][mt][1]=0.f; acc[nt][mt][2]=0.f; acc[nt][mt][3]=0.f; }
        #pragma unroll
        for (int kh = 0; kh < 2; kh++) {
            uint32_t afr[2][4][4];
            #pragma unroll
            for (int mt = 0; mt < 2; mt++)
                #pragma unroll
                for (int j = 0; j < 4; j++)
                    ldsm_x4(afr[mt][j], sb + xcur + amBase + (uint32_t)(mt * 16) * ROW_B
                                        + (uint32_t)(kh * 4 + j) * 32);
            #pragma unroll
            for (int nt = 0; nt < 4; nt++) {
                uint32_t b[2][4];
                ldsm_x4_t(b[0], wl1 + (uint32_t)(kh * 2 + 0) * (32 * ROW_B) + nt * 16);
                ldsm_x4_t(b[1], wl1 + (uint32_t)(kh * 2 + 1) * (32 * ROW_B) + nt * 16);
                #pragma unroll
                for (int mt = 0; mt < 2; mt++)
                    #pragma unroll
                    for (int j = 0; j < 4; j++)
                        mma16816(acc[nt][mt], afr[mt][j], &b[j >> 1][(j & 1) * 2]);
            }
        }

        // ---- stage next slice's x into other buffer ----
        if (hn) {
            #pragma unroll
            for (int i = 0; i < 4; i++)
                *(uint2*)(smem + xnxt + (srow + i) * ROW_B + lane * 8) =
                    make_uint2(packbf(v0[i].x, v0[i].y), packbf(v0[i].z, v0[i].w));
            #pragma unroll
            for (int i = 4; i < 8; i++) {
                float4 v = *(const float4*)(xnp + (size_t)i * 128);
                *(uint2*)(smem + xnxt + (srow + i) * ROW_B + lane * 8) =
                    make_uint2(packbf(v.x, v.y), packbf(v.z, v.w));
            }
        }

        // ---- epilogue 1: H quarter = tanh(acc + b1) -> H strip ----
        #pragma unroll
        for (int nt = 0; nt < 4; nt++) {
            float2 bb = *(const float2*)(fb1 + nt * 8);
            int c = qw * 32 + nt * 8 + t2;
            #pragma unroll
            for (int mt = 0; mt < 2; mt++) {
                uint32_t p0 = packbf(tanh_fast(acc[nt][mt][0] + bb.x),
                                     tanh_fast(acc[nt][mt][1] + bb.y));
                uint32_t p1 = packbf(tanh_fast(acc[nt][mt][2] + bb.x),
                                     tanh_fast(acc[nt][mt][3] + bb.y));
                *(uint32_t*)(smem + hoff + (mt * 16 + g) * ROW_B + c * 2) = p0;
                *(uint32_t*)(smem + hoff + (mt * 16 + g + 8) * ROW_B + c * 2) = p1;
            }
        }
        asm volatile("bar.sync %0, 128;" :: "r"(barid) : "memory");   // H + next-x ready

        // ---- GEMM2: acc = H(32 rows) @ W2(:, quarter) ----
        #pragma unroll
        for (int nt = 0; nt < 4; nt++)
            #pragma unroll
            for (int mt = 0; mt < 2; mt++)
                { acc[nt][mt][0]=0.f; acc[nt][mt][1]=0.f; acc[nt][mt][2]=0.f; acc[nt][mt][3]=0.f; }
        #pragma unroll
        for (int kh = 0; kh < 2; kh++) {
            uint32_t afr[2][4][4];
            #pragma unroll
            for (int mt = 0; mt < 2; mt++)
                #pragma unroll
                for (int j = 0; j < 4; j++)
                    ldsm_x4(afr[mt][j], sb + hoff + amBase + (uint32_t)(mt * 16) * ROW_B
                                        + (uint32_t)(kh * 4 + j) * 32);
            #pragma unroll
            for (int nt = 0; nt < 4; nt++) {
                uint32_t b[2][4];
                ldsm_x4_t(b[0], wl2 + (uint32_t)(kh * 2 + 0) * (32 * ROW_B) + nt * 16);
                ldsm_x4_t(b[1], wl2 + (uint32_t)(kh * 2 + 1) * (32 * ROW_B) + nt * 16);
                #pragma unroll
                for (int mt = 0; mt < 2; mt++)
                    #pragma unroll
                    for (int j = 0; j < 4; j++)
                        mma16816(acc[nt][mt], afr[mt][j], &b[j >> 1][(j & 1) * 2]);
            }
        }

        // ---- epilogue 2: rotation-scaling on exact fp32 x from gmem ----
        #pragma unroll
        for (int nt = 0; nt < 4; nt++) {
            int c = qw * 32 + nt * 8 + t2;
            float2 bb = *(const float2*)(fb2 + nt * 8);
            #pragma unroll
            for (int mt = 0; mt < 2; mt++)
                #pragma unroll
                for (int half = 0; half < 2; half++) {
                    float mu = acc[nt][mt][half * 2 + 0] + bb.x;
                    float om = acc[nt][mt][half * 2 + 1] + bb.y;
                    size_t r = rbase + (size_t)(mt * 16 + g + half * 8);
                    float2 xv = *(const float2*)(x + r * 128 + c);
                    float z  = DT_STEP * mu;
                    float e  = fmaf(z, fmaf(z, fmaf(z, 1.f / 6.f, 0.5f), 1.f), 1.f);
                    float wv = DT_STEP * om;
                    float w2 = wv * wv;
                    float sn = wv * fmaf(w2, -1.f / 6.f, 1.f);
                    float cs = fmaf(w2, fmaf(w2, 1.f / 24.f, -0.5f), 1.f);
                    float2 o;
                    o.x = e * (cs * xv.x - sn * xv.y);
                    o.y = e * (sn * xv.x + cs * xv.y);
                    *(float2*)(out + r * 128 + c) = o;
                }
        }
        asm volatile("bar.sync %0, 128;" :: "r"(barid) : "memory");   // strip/H reuse safe
        buf ^= 1;
    }
}

// ---------------- launch ----------------
extern "C" void kernel_launch(void* const* d_in, const int* in_sizes, int n_in,
                              void* d_out, int out_size) {
    const float* x  = (const float*)d_in[0];
    const float* W1 = (const float*)d_in[1];
    const float* b1 = (const float*)d_in[2];
    const float* W2 = (const float*)d_in[3];
    const float* b2 = (const float*)d_in[4];
    float* out = (float*)d_out;

    cudaFuncSetAttribute(koopman_quad2,
                         cudaFuncAttributeMaxDynamicSharedMemorySize, S_TOT);
    koopman_quad2<<<GRID_SMS, 512, S_TOT>>>(x, W1, b1, W2, b2, out);
}